// round 2
// baseline (speedup 1.0000x reference)
#include <cuda_runtime.h>
#include <float.h>
#include <math.h>

// TD_BERT: ragged span max-pool over sentence_embed + tiny FC(1024->3) + tanh.
// B=256, S=512, D=1024, O=3. Span length is <= 8 rows, so we only touch the
// span rows (~9 MB total traffic), never the full 512 MB tensor.
// One CTA per example; thread t owns channels 4t..4t+3 (float4 loads).

#define TB_S 512
#define TB_D 1024
#define TB_O 3
#define NTHREADS 256

__global__ void __launch_bounds__(NTHREADS, 1)
td_bert_kernel(const float* __restrict__ embed,
               const int* __restrict__ t_ids,
               const int* __restrict__ left_ids,
               const float* __restrict__ fc_w,
               const float* __restrict__ fc_b,
               float* __restrict__ out) {
    const int b    = blockIdx.x;
    const int tid  = threadIdx.x;         // 0..255
    const int warp = tid >> 5;
    const int lane = tid & 31;

    __shared__ int   s_lc[8], s_tc[8];
    __shared__ int   s_span[2];           // start, end
    __shared__ float s_red[8 * TB_O];

    // ---- 1. prefix counts -> span [start, end) ----
    const int2* lb = (const int2*)(left_ids + b * TB_S);
    const int2* tb = (const int2*)(t_ids    + b * TB_S);
    const int2 lv = lb[tid];
    const int2 tv = tb[tid];
    int lc = (lv.x != 0) + (lv.y != 0);
    int tc = (tv.x != 0) + (tv.y != 0);
    #pragma unroll
    for (int off = 16; off; off >>= 1) {
        lc += __shfl_down_sync(0xffffffffu, lc, off);
        tc += __shfl_down_sync(0xffffffffu, tc, off);
    }
    if (lane == 0) { s_lc[warp] = lc; s_tc[warp] = tc; }
    __syncthreads();
    if (tid == 0) {
        int L = 0, T = 0;
        #pragma unroll
        for (int w = 0; w < 8; w++) { L += s_lc[w]; T += s_tc[w]; }
        const int left_len   = L - 1;
        const int target_len = T - 2;
        s_span[0] = left_len;                // start
        s_span[1] = left_len + target_len;   // end
    }
    __syncthreads();
    const int start = s_span[0];
    const int end   = s_span[1];

    // ---- 2. fused span-max (float4) + FC partial dot ----
    const float* eb = embed + (size_t)b * TB_S * TB_D;
    const int d0 = tid * 4;               // this thread's 4 channels
    float4 m = make_float4(-FLT_MAX, -FLT_MAX, -FLT_MAX, -FLT_MAX);
    for (int r = start; r < end; r++) {   // <= 8 iterations, independent loads
        const float4 v = *(const float4*)(eb + r * TB_D + d0);
        m.x = fmaxf(m.x, v.x);
        m.y = fmaxf(m.y, v.y);
        m.z = fmaxf(m.z, v.z);
        m.w = fmaxf(m.w, v.w);
    }

    float acc0 = 0.f, acc1 = 0.f, acc2 = 0.f;
    const float mv[4] = {m.x, m.y, m.z, m.w};
    #pragma unroll
    for (int j = 0; j < 4; j++) {
        const float* wr = fc_w + (d0 + j) * TB_O;
        acc0 += mv[j] * wr[0];
        acc1 += mv[j] * wr[1];
        acc2 += mv[j] * wr[2];
    }

    // ---- 3. block reduce the 3 logits ----
    #pragma unroll
    for (int off = 16; off; off >>= 1) {
        acc0 += __shfl_down_sync(0xffffffffu, acc0, off);
        acc1 += __shfl_down_sync(0xffffffffu, acc1, off);
        acc2 += __shfl_down_sync(0xffffffffu, acc2, off);
    }
    if (lane == 0) {
        s_red[warp * TB_O + 0] = acc0;
        s_red[warp * TB_O + 1] = acc1;
        s_red[warp * TB_O + 2] = acc2;
    }
    __syncthreads();
    if (tid < TB_O) {
        float s = 0.f;
        #pragma unroll
        for (int w = 0; w < 8; w++) s += s_red[w * TB_O + tid];
        out[b * TB_O + tid] = tanhf(s + fc_b[tid]);
    }
}

extern "C" void kernel_launch(void* const* d_in, const int* in_sizes, int n_in,
                              void* d_out, int out_size) {
    const float* embed    = (const float*)d_in[0];  // [256,512,1024]
    const int*   t_ids    = (const int*)  d_in[1];  // [256,512]
    const int*   left_ids = (const int*)  d_in[2];  // [256,512]
    const float* fc_w     = (const float*)d_in[3];  // [1024,3]
    const float* fc_b     = (const float*)d_in[4];  // [3]
    float*       out      = (float*)d_out;          // [256,3]

    const int B = in_sizes[1] / TB_S;               // 256
    td_bert_kernel<<<B, NTHREADS>>>(embed, t_ids, left_ids, fc_w, fc_b, out);
}

// round 4
// speedup vs baseline: 1.2963x; 1.2963x over previous
#include <cuda_runtime.h>
#include <float.h>
#include <math.h>

// TD_BERT: ragged span max-pool + FC(1024->3) + tanh. B=256,S=512,D=1024,O=3.
// Latency-bound tiny kernel. Strategy: 1 wave (2 examples per 512-thread CTA,
// grid=128 < 148 SMs), fully-batched span row loads (span <= 8 rows, unrolled
// with clamp -> MLP=8), fc_w prefetched before the barrier, REDUX for counts.

#define TB_S 512
#define TB_D 1024
#define TB_O 3

__global__ void __launch_bounds__(512, 1)
td_bert_kernel(const float* __restrict__ embed,
               const int* __restrict__ t_ids,
               const int* __restrict__ left_ids,
               const float* __restrict__ fc_w,
               const float* __restrict__ fc_b,
               float* __restrict__ out, int B) {
    const int tid  = threadIdx.x;         // 0..511
    const int sub  = tid >> 8;            // which example half (0/1)
    const int stid = tid & 255;           // thread id within example
    const int warp = tid >> 5;            // 0..15
    const int lane = tid & 31;
    int b = blockIdx.x * 2 + sub;
    const int bsafe = (b < B) ? b : (B - 1);

    __shared__ int   s_cnt[16];           // warps 0-3: lc ex0, 4-7: tc ex0, 8-11: lc ex1, 12-15: tc ex1
    __shared__ float s_red[16 * TB_O];

    // ---- phase 1: id counts (int4, split halves) + fc_w prefetch ----
    const int* arr = ((stid < 128) ? left_ids : t_ids) + bsafe * TB_S;
    const int4 iv  = ((const int4*)arr)[stid & 127];
    int c = (iv.x != 0) + (iv.y != 0) + (iv.z != 0) + (iv.w != 0);

    const int d0 = stid * 4;              // this thread's 4 channels
    // prefetch 12 fc_w coeffs (16B-aligned: d0*3*4 = stid*48 bytes)
    const float4 w0 = *(const float4*)(fc_w + d0 * TB_O);
    const float4 w1 = *(const float4*)(fc_w + d0 * TB_O + 4);
    const float4 w2 = *(const float4*)(fc_w + d0 * TB_O + 8);

    c = __reduce_add_sync(0xffffffffu, c);   // single REDUX.SUM
    if (lane == 0) s_cnt[warp] = c;
    __syncthreads();

    // all threads redundantly compute span (saves a sync + rebroadcast)
    const int base = sub * 8;
    const int L = s_cnt[base + 0] + s_cnt[base + 1] + s_cnt[base + 2] + s_cnt[base + 3];
    const int T = s_cnt[base + 4] + s_cnt[base + 5] + s_cnt[base + 6] + s_cnt[base + 7];
    const int start = L - 1;              // left_len
    const int last  = L + T - 4;          // start + target_len - 1  (>= start)

    // ---- phase 2: span max, 8 independent clamped LDG.128 ----
    const float* eb = embed + (size_t)bsafe * TB_S * TB_D + d0;
    float4 m = *(const float4*)(eb + start * TB_D);
    #pragma unroll
    for (int i = 1; i < 8; i++) {
        int r = start + i;
        r = (r > last) ? last : r;        // clamp: duplicate fmax is harmless
        const float4 v = *(const float4*)(eb + r * TB_D);
        m.x = fmaxf(m.x, v.x);
        m.y = fmaxf(m.y, v.y);
        m.z = fmaxf(m.z, v.z);
        m.w = fmaxf(m.w, v.w);
    }

    // ---- fused FC partial dot (fc_w already in registers) ----
    float acc0 = m.x * w0.x + m.y * w0.w + m.z * w1.z + m.w * w2.y;
    float acc1 = m.x * w0.y + m.y * w1.x + m.z * w1.w + m.w * w2.z;
    float acc2 = m.x * w0.z + m.y * w1.y + m.z * w2.x + m.w * w2.w;

    // ---- block reduce the 3 logits per example ----
    #pragma unroll
    for (int off = 16; off; off >>= 1) {
        acc0 += __shfl_down_sync(0xffffffffu, acc0, off);
        acc1 += __shfl_down_sync(0xffffffffu, acc1, off);
        acc2 += __shfl_down_sync(0xffffffffu, acc2, off);
    }
    if (lane == 0) {
        s_red[warp * TB_O + 0] = acc0;
        s_red[warp * TB_O + 1] = acc1;
        s_red[warp * TB_O + 2] = acc2;
    }
    __syncthreads();
    if (stid < TB_O && b < B) {
        float s = 0.f;
        #pragma unroll
        for (int w = 0; w < 8; w++) s += s_red[(base + w) * TB_O + stid];
        out[b * TB_O + stid] = tanhf(s + fc_b[stid]);
    }
}

extern "C" void kernel_launch(void* const* d_in, const int* in_sizes, int n_in,
                              void* d_out, int out_size) {
    const float* embed    = (const float*)d_in[0];  // [256,512,1024]
    const int*   t_ids    = (const int*)  d_in[1];  // [256,512]
    const int*   left_ids = (const int*)  d_in[2];  // [256,512]
    const float* fc_w     = (const float*)d_in[3];  // [1024,3]
    const float* fc_b     = (const float*)d_in[4];  // [3]
    float*       out      = (float*)d_out;          // [256,3]

    const int B = in_sizes[1] / TB_S;               // 256
    td_bert_kernel<<<(B + 1) / 2, 512>>>(embed, t_ids, left_ids, fc_w, fc_b, out, B);
}